// round 16
// baseline (speedup 1.0000x reference)
#include <cuda_runtime.h>
#include <cuda_fp16.h>
#include <cstdint>
#include <math.h>

#define B_    8
#define N_    1024
#define DIM_  768
#define NH_   12
#define HD_   64
#define QKVC_ 2304
#define MROWS (B_*N_)   // 8192

// ---------------- scratch (__device__ globals) ------------------------------
static __device__ __half g_xf[(size_t)MROWS * DIM_];
static __device__ __half g_af[(size_t)MROWS * DIM_];
static __device__ __half g_wqT[(size_t)QKVC_ * DIM_];
static __device__ __half g_wpT[(size_t)DIM_ * DIM_];
// per-head fp16 qkv: [bh][n][d], bh = b*12+h
static __device__ __half g_qf[(size_t)MROWS * DIM_];
static __device__ __half g_kf[(size_t)MROWS * DIM_];
static __device__ __half g_vf[(size_t)MROWS * DIM_];

// ---------------- helpers ----------------------------------------------------
__device__ __forceinline__ uint32_t smem_u32(const void* p) {
    uint32_t a;
    asm("{ .reg .u64 t; cvta.to.shared.u64 t, %1; cvt.u32.u64 %0, t; }" : "=r"(a) : "l"(p));
    return a;
}
__device__ __forceinline__ void ldsm_x4(uint32_t* r, uint32_t addr) {
    asm volatile("ldmatrix.sync.aligned.m8n8.x4.shared.b16 {%0,%1,%2,%3}, [%4];"
                 : "=r"(r[0]), "=r"(r[1]), "=r"(r[2]), "=r"(r[3]) : "r"(addr));
}
__device__ __forceinline__ void ldsm_x4_t(uint32_t* r, uint32_t addr) {
    asm volatile("ldmatrix.sync.aligned.m8n8.x4.trans.shared.b16 {%0,%1,%2,%3}, [%4];"
                 : "=r"(r[0]), "=r"(r[1]), "=r"(r[2]), "=r"(r[3]) : "r"(addr));
}
// volatile: source order == issue order (R5/R7 schedule beats ptxas reordering)
__device__ __forceinline__ void mma_f16(float* c, const uint32_t* a,
                                        uint32_t b0, uint32_t b1) {
    asm volatile("mma.sync.aligned.m16n8k16.row.col.f32.f16.f16.f32 "
        "{%0,%1,%2,%3}, {%4,%5,%6,%7}, {%8,%9}, {%0,%1,%2,%3};"
        : "+f"(c[0]), "+f"(c[1]), "+f"(c[2]), "+f"(c[3])
        : "r"(a[0]), "r"(a[1]), "r"(a[2]), "r"(a[3]), "r"(b0), "r"(b1));
}
__device__ __forceinline__ uint32_t pack_f16x2(float lo, float hi) {
    uint32_t d;
    asm("cvt.rn.f16x2.f32 %0, %1, %2;" : "=r"(d) : "f"(hi), "f"(lo));
    return d;
}
#define CP_ASYNC16(dst, src) \
    asm volatile("cp.async.cg.shared.global [%0], [%1], 16;" :: "r"(dst), "l"(src) : "memory")
#define CP_COMMIT() asm volatile("cp.async.commit_group;" ::: "memory")
#define CP_WAIT(n)  asm volatile("cp.async.wait_group %0;" :: "n"(n) : "memory")

// ---------------- fused prologue: convert x + transpose weights (fp16) ------
__global__ void __launch_bounds__(256) prologue(
    const float* __restrict__ x,
    const float* __restrict__ w_qkv, const float* __restrict__ w_proj,
    __half* __restrict__ xf, __half* __restrict__ wqT, __half* __restrict__ wpT)
{
    const int bid = blockIdx.x;
    if (bid < 6144) {
        int i = bid * 256 + threadIdx.x;
        float4 v = ((const float4*)x)[i];
        uint32_t h0 = pack_f16x2(v.x, v.y);
        uint32_t h1 = pack_f16x2(v.z, v.w);
        ((uint32_t*)xf)[2 * i]     = h0;
        ((uint32_t*)xf)[2 * i + 1] = h1;
        return;
    }
    __shared__ float t[32][33];
    const float* W; __half* WT;
    int K = 768, Nc, bx, by;
    if (bid < 6144 + 1728) {
        int id = bid - 6144;
        W = w_qkv; WT = wqT; Nc = QKVC_;
        bx = id % 72; by = id / 72;
    } else {
        int id = bid - 7872;
        W = w_proj; WT = wpT; Nc = DIM_;
        bx = id % 24; by = id / 24;
    }
    const int n0 = bx * 32, k0 = by * 32;
    const int tx = threadIdx.x & 31, ty = threadIdx.x >> 5;
#pragma unroll
    for (int i = 0; i < 32; i += 8)
        t[ty + i][tx] = W[(size_t)(k0 + ty + i) * Nc + n0 + tx];
    __syncthreads();
#pragma unroll
    for (int i = 0; i < 32; i += 8)
        WT[(size_t)(n0 + ty + i) * K + k0 + tx] = __float2half_rn(t[tx][ty + i]);
}

// ---------------- HMMA fp16 GEMM (BK=64, 3-stage cp.async, batched ldsm) ----
#define GT       16384
#define GSTAGE   (2 * GT)            // A, B = 32768
#define GEMM_SMEM (3 * GSTAGE)       // 98304

template<int MODE>
__global__ void __launch_bounds__(256, 2) gemm_f16(
    const __half* __restrict__ A, const __half* __restrict__ BT,
    const float* __restrict__ bias, float* __restrict__ C, int Nc, int K,
    __half* qf_, __half* kf_, __half* vf_)
{
    extern __shared__ char gsm[];
    const uint32_t sb = smem_u32(gsm);
    const int tid = threadIdx.x, wid = tid >> 5, lid = tid & 31;
    const int wm = wid >> 1, wn = wid & 1;
    const int m0 = blockIdx.y << 7, n0 = blockIdx.x << 7;

    const __half* pA = A  + (size_t)m0 * K;
    const __half* pB = BT + (size_t)n0 * K;

    float acc[2][8][4];
#pragma unroll
    for (int i = 0; i < 2; ++i)
#pragma unroll
        for (int j = 0; j < 8; ++j)
#pragma unroll
            for (int k = 0; k < 4; ++k) acc[i][j][k] = 0.f;

    const int nkt = K >> 6;   // BK = 64

    const int prow = tid >> 3, pc = tid & 7;
#define GPF(kt, stage) do {                                                      \
    uint32_t s0 = sb + (stage) * GSTAGE;                                         \
    _Pragma("unroll")                                                            \
    for (int hf = 0; hf < 4; ++hf) {                                             \
        int row = prow + hf * 32;                                                \
        uint32_t d = s0 + row * 128 + ((pc ^ (row & 7)) << 4);                   \
        size_t go = (size_t)row * K + (size_t)(kt) * 64 + pc * 8;                \
        CP_ASYNC16(d,      pA + go);                                             \
        CP_ASYNC16(d + GT, pB + go);                                             \
    }                                                                            \
    CP_COMMIT();                                                                 \
} while (0)

    GPF(0, 0);
    GPF(1, 1);

    uint32_t abase[2], asw[2], bbase[4], bsw[4];
    const int acb = lid >> 4;
    const int bcb = (lid >> 3) & 1;
#pragma unroll
    for (int im = 0; im < 2; ++im) {
        int ar = wm * 32 + (lid & 15) + im * 16;
        abase[im] = ar * 128;
        asw[im] = ar & 7;
    }
#pragma unroll
    for (int p = 0; p < 4; ++p) {
        int br = wn * 64 + (lid & 7) + ((lid >> 4) << 3) + p * 16;
        bbase[p] = br * 128;
        bsw[p] = br & 7;
    }

    int scur = 0;
    for (int kt = 0; kt < nkt; ++kt) {
        if (kt == nkt - 1) { CP_WAIT(0); } else { CP_WAIT(1); }
        __syncthreads();
        const uint32_t st = sb + scur * GSTAGE;

#pragma unroll
        for (int kc = 0; kc < 4; ++kc) {
            // batch all fragment loads: LSU pipelines 6 ldsm; MMA burst follows
            uint32_t ah[2][4], b4[4][4];
#pragma unroll
            for (int im = 0; im < 2; ++im)
                ldsm_x4(ah[im], st + abase[im]
                                + (((uint32_t)(kc * 2 + acb) ^ asw[im]) << 4));
#pragma unroll
            for (int p = 0; p < 4; ++p)
                ldsm_x4(b4[p], st + GT + bbase[p]
                               + (((uint32_t)(kc * 2 + bcb) ^ bsw[p]) << 4));
#pragma unroll
            for (int p = 0; p < 4; ++p) {
                const int nt0 = p * 2, nt1 = p * 2 + 1;
                mma_f16(acc[0][nt0], ah[0], b4[p][0], b4[p][1]);
                mma_f16(acc[1][nt0], ah[1], b4[p][0], b4[p][1]);
                mma_f16(acc[0][nt1], ah[0], b4[p][2], b4[p][3]);
                mma_f16(acc[1][nt1], ah[1], b4[p][2], b4[p][3]);
            }
        }
        if (kt + 2 < nkt) {
            int spf = scur + 2; if (spf >= 3) spf -= 3;
            GPF(kt + 2, spf);
        }
        if (++scur == 3) scur = 0;
    }
#undef GPF

    const int g = lid >> 2, q = lid & 3;
    if (MODE == 0) {
#pragma unroll
        for (int im = 0; im < 2; ++im) {
            const int row0 = m0 + wm * 32 + im * 16 + g;
#pragma unroll
            for (int nt = 0; nt < 8; ++nt) {
                const int col = n0 + wn * 64 + nt * 8 + q * 2;
                float b0 = 0.f, b1 = 0.f;
                if (bias) { b0 = bias[col]; b1 = bias[col + 1]; }
                float2 v0 = make_float2(acc[im][nt][0] + b0, acc[im][nt][1] + b1);
                float2 v1 = make_float2(acc[im][nt][2] + b0, acc[im][nt][3] + b1);
                *(float2*)(C + (size_t)row0 * Nc + col)       = v0;
                *(float2*)(C + (size_t)(row0 + 8) * Nc + col) = v1;
            }
        }
    } else {
        // fp16 qkv epilogue; q pre-scaled by 0.125*log2(e) for exp2-softmax
#pragma unroll
        for (int im = 0; im < 2; ++im) {
            const int row0 = m0 + wm * 32 + im * 16 + g;
#pragma unroll
            for (int nt = 0; nt < 8; ++nt) {
                const int col = n0 + wn * 64 + nt * 8 + q * 2;
                const int sect = col / 768, rem = col - sect * 768;
                const int h = rem >> 6, d = rem & 63;
                __half* dst;
                float sc;
                if (sect == 0)      { dst = qf_; sc = 0.18033688f; }
                else if (sect == 1) { dst = kf_; sc = 1.0f; }
                else                { dst = vf_; sc = 1.0f; }
#pragma unroll
                for (int rr = 0; rr < 2; ++rr) {
                    const int row = row0 + rr * 8;
                    uint32_t hh = pack_f16x2(acc[im][nt][rr * 2 + 0] * sc,
                                             acc[im][nt][rr * 2 + 1] * sc);
                    size_t off = ((size_t)(row >> 10) * 12 + h) * 65536
                               + (size_t)(row & 1023) * 64 + d;
                    *(uint32_t*)(dst + off) = hh;
                }
            }
        }
    }
}

// ---------------- fp16 flash attention (Bk=128, batched ldsm) ---------------
#define AT2     16384                // one K or V tile (128 rows x 128B fp16)
#define ASTG    (2 * AT2)            // K, V = 32768
#define ATTN_SMEM (3 * ASTG)         // 98304

__global__ void __launch_bounds__(256, 2) attn_hmma(
    const __half* __restrict__ qf_, const __half* __restrict__ kf_,
    const __half* __restrict__ vf_, __half* __restrict__ af_)
{
    extern __shared__ char sm_[];
    const uint32_t sb = smem_u32(sm_);
    const int tid = threadIdx.x, wid = tid >> 5, lid = tid & 31;
    const int g = lid >> 2, q = lid & 3;
    const int bh = blockIdx.y, qt = blockIdx.x;

    const size_t hb = (size_t)bh << 16;
    const __half* Qf = qf_ + hb + (size_t)qt * 128 * 64;
    const __half* Kf = kf_ + hb;
    const __half* Vf = vf_ + hb;

#pragma unroll
    for (int it = 0; it < 4; ++it) {
        int idx = tid + it * 256;
        int row = idx >> 3, c = idx & 7;
        uint32_t d = row * 128 + ((c ^ (row & 7)) << 4);
        *(uint4*)(sm_ + d) = *(const uint4*)(Qf + (size_t)row * 64 + c * 8);
    }
    __syncthreads();

    uint32_t qf[4][4];
    {
        const int arq = wid * 16 + (lid & 15);
        const uint32_t qbase = arq * 128;
        const uint32_t qsw = arq & 7;
        const int acb = lid >> 4;
#pragma unroll
        for (int kc = 0; kc < 4; ++kc)
            ldsm_x4(qf[kc], sb + qbase + (((uint32_t)(kc * 2 + acb) ^ qsw) << 4));
    }
    __syncthreads();

    float lrow[2] = {0.f, 0.f};
    float o[8][4];
#pragma unroll
    for (int i = 0; i < 8; ++i)
#pragma unroll
        for (int j = 0; j < 4; ++j) o[i][j] = 0.f;

    const int prow = tid >> 3, pc = tid & 7;
#define APF(kt, stage) do {                                                       \
    uint32_t s0 = sb + (stage) * ASTG;                                            \
    _Pragma("unroll")                                                             \
    for (int hf = 0; hf < 4; ++hf) {                                              \
        int row = prow + hf * 32;                                                 \
        uint32_t d = s0 + row * 128 + ((pc ^ (row & 7)) << 4);                    \
        size_t go = (size_t)((kt) * 128 + row) * 64 + pc * 8;                     \
        CP_ASYNC16(d,       Kf + go);                                             \
        CP_ASYNC16(d + AT2, Vf + go);                                             \
    }                                                                             \
    CP_COMMIT();                                                                  \
} while (0)

    APF(0, 0);
    APF(1, 1);

    uint32_t kbase[4], ksw[4], vbase[4], vsw[4];
    const int bcb = (lid >> 3) & 1;
    const int vcb = lid >> 4;
#pragma unroll
    for (int p = 0; p < 4; ++p) {
        int br = (lid & 7) + ((lid >> 4) << 3) + p * 16;
        kbase[p] = br * 128; ksw[p] = br & 7;
        int vr = (lid & 15) + p * 16;
        vbase[p] = vr * 128; vsw[p] = vr & 7;
    }

    int scur = 0;
    for (int kt = 0; kt < 8; ++kt) {
        if (kt == 7) { CP_WAIT(0); } else { CP_WAIT(1); }
        __syncthreads();
        const uint32_t st = sb + scur * ASTG;

#pragma unroll
        for (int half = 0; half < 2; ++half) {
            const uint32_t ho = half * 8192;   // 64 key-rows * 128B

            // ---- S = Q K^T (fp16), batched K-fragment loads per kc ----
            float s[8][4];
#pragma unroll
            for (int i = 0; i < 8; ++i)
#pragma unroll
                for (int j = 0; j < 4; ++j) s[i][j] = 0.f;

#pragma unroll
            for (int kc = 0; kc < 4; ++kc) {
                uint32_t kh4[4][4];
#pragma unroll
                for (int p = 0; p < 4; ++p)
                    ldsm_x4(kh4[p], st + ho + kbase[p]
                                    + (((uint32_t)(kc * 2 + bcb) ^ ksw[p]) << 4));
#pragma unroll
                for (int p = 0; p < 4; ++p) {
                    mma_f16(s[2 * p],     qf[kc], kh4[p][0], kh4[p][1]);
                    mma_f16(s[2 * p + 1], qf[kc], kh4[p][2], kh4[p][3]);
                }
            }

            uint32_t pab[2][4];
#define PREP(t, buf) do {                                                         \
            float a0 = exp2f(s[2*(t)][0]),   a1 = exp2f(s[2*(t)][1]);             \
            float a2 = exp2f(s[2*(t)][2]),   a3 = exp2f(s[2*(t)][3]);             \
            float b0 = exp2f(s[2*(t)+1][0]), b1 = exp2f(s[2*(t)+1][1]);           \
            float b2 = exp2f(s[2*(t)+1][2]), b3 = exp2f(s[2*(t)+1][3]);           \
            lrow[0] += a0 + a1 + b0 + b1;                                         \
            lrow[1] += a2 + a3 + b2 + b3;                                         \
            pab[buf][0] = pack_f16x2(a0, a1);                                     \
            pab[buf][1] = pack_f16x2(a2, a3);                                     \
            pab[buf][2] = pack_f16x2(b0, b1);                                     \
            pab[buf][3] = pack_f16x2(b2, b3);                                     \
} while (0)

            PREP(0, 0);

            // ---- O += P V: batch 4 V-ldsm, PREP under load latency, 8 MMAs --
#pragma unroll
            for (int t = 0; t < 4; ++t) {
                const int cur = t & 1;
                uint32_t vh4[4][4];
#pragma unroll
                for (int p = 0; p < 4; ++p)
                    ldsm_x4_t(vh4[p], st + AT2 + ho + vbase[t]
                                      + (((uint32_t)(p * 2 + vcb) ^ vsw[t]) << 4));
                if (t < 3) PREP(t + 1, cur ^ 1);   // MUFU overlaps LSU
#pragma unroll
                for (int p = 0; p < 4; ++p) {
                    mma_f16(o[2 * p],     pab[cur], vh4[p][0], vh4[p][1]);
                    mma_f16(o[2 * p + 1], pab[cur], vh4[p][2], vh4[p][3]);
                }
            }
#undef PREP
        }

        if (kt + 2 < 8) {
            int spf = scur + 2; if (spf >= 3) spf -= 3;
            APF(kt + 2, spf);
        }
        if (++scur == 3) scur = 0;
    }
#undef APF

    // ---- epilogue: one row-sum reduction, normalize, fp16 write ----
#pragma unroll
    for (int r = 0; r < 2; ++r) {
        lrow[r] += __shfl_xor_sync(0xffffffffu, lrow[r], 1);
        lrow[r] += __shfl_xor_sync(0xffffffffu, lrow[r], 2);
    }
    const int b = bh / NH_, h = bh - b * NH_;
    const float inv0 = 1.f / lrow[0], inv1 = 1.f / lrow[1];
    const int row0 = b * 1024 + qt * 128 + wid * 16 + g;
#pragma unroll
    for (int nt = 0; nt < 8; ++nt) {
        const int col = h * 64 + nt * 8 + q * 2;
        uint32_t hh = pack_f16x2(o[nt][0] * inv0, o[nt][1] * inv0);
        *(uint32_t*)(af_ + (size_t)row0 * DIM_ + col) = hh;
        hh = pack_f16x2(o[nt][2] * inv1, o[nt][3] * inv1);
        *(uint32_t*)(af_ + (size_t)(row0 + 8) * DIM_ + col) = hh;
    }
}

// ---------------------------------------------------------------------------
extern "C" void kernel_launch(void* const* d_in, const int* in_sizes, int n_in,
                              void* d_out, int out_size)
{
    const float* x      = (const float*)d_in[0];
    const float* w_qkv  = (const float*)d_in[1];
    const float* w_proj = (const float*)d_in[2];
    const float* b_proj = (const float*)d_in[3];
    float* out = (float*)d_out;

    __half *xf, *af, *wqT, *wpT, *qf, *kf, *vf;
    cudaGetSymbolAddress((void**)&xf, g_xf);
    cudaGetSymbolAddress((void**)&af, g_af);
    cudaGetSymbolAddress((void**)&wqT, g_wqT);
    cudaGetSymbolAddress((void**)&wpT, g_wpT);
    cudaGetSymbolAddress((void**)&qf, g_qf);
    cudaGetSymbolAddress((void**)&kf, g_kf);
    cudaGetSymbolAddress((void**)&vf, g_vf);

    cudaFuncSetAttribute((const void*)gemm_f16<1>,
        cudaFuncAttributeMaxDynamicSharedMemorySize, GEMM_SMEM);
    cudaFuncSetAttribute((const void*)gemm_f16<0>,
        cudaFuncAttributeMaxDynamicSharedMemorySize, GEMM_SMEM);
    cudaFuncSetAttribute((const void*)attn_hmma,
        cudaFuncAttributeMaxDynamicSharedMemorySize, ATTN_SMEM);

    const int M = MROWS;

    prologue<<<8448, 256>>>(x, w_qkv, w_proj, xf, wqT, wpT);

    // 1) QKV projection (fp16, BK=64) -> fp16 per-head q/k/v (q pre-scaled)
    gemm_f16<1><<<dim3(QKVC_ / 128, M / 128), 256, GEMM_SMEM>>>(
        xf, wqT, nullptr, nullptr, QKVC_, DIM_, qf, kf, vf);

    // 2) fp16 flash attention (Bk=128) -> fp16 proj input
    attn_hmma<<<dim3(N_ / 128, B_ * NH_), 256, ATTN_SMEM>>>(
        qf, kf, vf, af);

    // 3) output projection (fp16, BK=64) + bias -> out
    gemm_f16<0><<<dim3(DIM_ / 128, M / 128), 256, GEMM_SMEM>>>(
        af, wpT, b_proj, out, DIM_, DIM_, nullptr, nullptr, nullptr);
}

// round 17
// speedup vs baseline: 1.0038x; 1.0038x over previous
#include <cuda_runtime.h>
#include <cuda_fp16.h>
#include <cstdint>
#include <math.h>

#define B_    8
#define N_    1024
#define DIM_  768
#define NH_   12
#define HD_   64
#define QKVC_ 2304
#define MROWS (B_*N_)   // 8192

// ---------------- scratch (__device__ globals) ------------------------------
static __device__ __half g_xf[(size_t)MROWS * DIM_];
static __device__ __half g_af[(size_t)MROWS * DIM_];
static __device__ __half g_wqT[(size_t)QKVC_ * DIM_];
static __device__ __half g_wpT[(size_t)DIM_ * DIM_];
// per-head fp16 qkv: [bh][n][d], bh = b*12+h
static __device__ __half g_qf[(size_t)MROWS * DIM_];
static __device__ __half g_kf[(size_t)MROWS * DIM_];
static __device__ __half g_vf[(size_t)MROWS * DIM_];

// ---------------- helpers ----------------------------------------------------
__device__ __forceinline__ uint32_t smem_u32(const void* p) {
    uint32_t a;
    asm("{ .reg .u64 t; cvta.to.shared.u64 t, %1; cvt.u32.u64 %0, t; }" : "=r"(a) : "l"(p));
    return a;
}
__device__ __forceinline__ void ldsm_x4(uint32_t* r, uint32_t addr) {
    asm volatile("ldmatrix.sync.aligned.m8n8.x4.shared.b16 {%0,%1,%2,%3}, [%4];"
                 : "=r"(r[0]), "=r"(r[1]), "=r"(r[2]), "=r"(r[3]) : "r"(addr));
}
__device__ __forceinline__ void ldsm_x4_t(uint32_t* r, uint32_t addr) {
    asm volatile("ldmatrix.sync.aligned.m8n8.x4.trans.shared.b16 {%0,%1,%2,%3}, [%4];"
                 : "=r"(r[0]), "=r"(r[1]), "=r"(r[2]), "=r"(r[3]) : "r"(addr));
}
// volatile: source order == issue order (R5/R7 schedule beats ptxas reordering)
__device__ __forceinline__ void mma_f16(float* c, const uint32_t* a,
                                        uint32_t b0, uint32_t b1) {
    asm volatile("mma.sync.aligned.m16n8k16.row.col.f32.f16.f16.f32 "
        "{%0,%1,%2,%3}, {%4,%5,%6,%7}, {%8,%9}, {%0,%1,%2,%3};"
        : "+f"(c[0]), "+f"(c[1]), "+f"(c[2]), "+f"(c[3])
        : "r"(a[0]), "r"(a[1]), "r"(a[2]), "r"(a[3]), "r"(b0), "r"(b1));
}
__device__ __forceinline__ uint32_t pack_f16x2(float lo, float hi) {
    uint32_t d;
    asm("cvt.rn.f16x2.f32 %0, %1, %2;" : "=r"(d) : "f"(hi), "f"(lo));
    return d;
}
#define CP_ASYNC16(dst, src) \
    asm volatile("cp.async.cg.shared.global [%0], [%1], 16;" :: "r"(dst), "l"(src) : "memory")
#define CP_COMMIT() asm volatile("cp.async.commit_group;" ::: "memory")
#define CP_WAIT(n)  asm volatile("cp.async.wait_group %0;" :: "n"(n) : "memory")

// ---------------- fused prologue v2: fat blocks ------------------------------
// [0,1536): x convert, grid-stride 4 float4/thread.
// [1536,1968): w_qkv 64x64 transpose tiles. [1968,2112): w_proj.
__global__ void __launch_bounds__(256) prologue(
    const float* __restrict__ x,
    const float* __restrict__ w_qkv, const float* __restrict__ w_proj,
    __half* __restrict__ xf, __half* __restrict__ wqT, __half* __restrict__ wpT)
{
    const int bid = blockIdx.x;
    if (bid < 1536) {
        // 1536 blocks * 256 thr * 4 float4 = 1,572,864 float4 = 8192*768 floats
        int base = bid * 1024 + threadIdx.x;
#pragma unroll
        for (int it = 0; it < 4; ++it) {
            int i = base + it * 256;
            float4 v = ((const float4*)x)[i];
            uint32_t h0 = pack_f16x2(v.x, v.y);
            uint32_t h1 = pack_f16x2(v.z, v.w);
            ((uint32_t*)xf)[2 * i]     = h0;
            ((uint32_t*)xf)[2 * i + 1] = h1;
        }
        return;
    }
    // 64x64 fp32 transpose tiles
    __shared__ float t[64][65];
    const float* W; __half* WT;
    int K = 768, Nc, bx, by;
    if (bid < 1968) {
        int id = bid - 1536;                 // 432 tiles
        W = w_qkv; WT = wqT; Nc = QKVC_;
        bx = id % 36; by = id / 36;          // 36 n-tiles x 12 k-tiles
    } else {
        int id = bid - 1968;                 // 144 tiles
        W = w_proj; WT = wpT; Nc = DIM_;
        bx = id % 12; by = id / 12;
    }
    const int n0 = bx * 64, k0 = by * 64;
    {
        const int c4 = threadIdx.x & 15;     // 16 float4 = 64 cols
        const int r  = threadIdx.x >> 4;     // 16 rows per pass
#pragma unroll
        for (int it = 0; it < 4; ++it) {
            int row = r + it * 16;
            float4 v = *(const float4*)(W + (size_t)(k0 + row) * Nc + n0 + c4 * 4);
            t[row][c4 * 4 + 0] = v.x;
            t[row][c4 * 4 + 1] = v.y;
            t[row][c4 * 4 + 2] = v.z;
            t[row][c4 * 4 + 3] = v.w;
        }
    }
    __syncthreads();
    {
        const int k4 = threadIdx.x & 15;     // 16 groups of 4 k
        const int n  = threadIdx.x >> 4;     // 16 n-rows per pass
#pragma unroll
        for (int it = 0; it < 4; ++it) {
            int nn = n + it * 16;
            uint32_t h0 = pack_f16x2(t[k4 * 4 + 0][nn], t[k4 * 4 + 1][nn]);
            uint32_t h1 = pack_f16x2(t[k4 * 4 + 2][nn], t[k4 * 4 + 3][nn]);
            uint32_t* dst = (uint32_t*)(WT + (size_t)(n0 + nn) * K + k0 + k4 * 4);
            dst[0] = h0;
            dst[1] = h1;
        }
    }
}

// ---------------- HMMA fp16 GEMM (BK=64, 3-stage cp.async; R15 form) --------
#define GT       16384
#define GSTAGE   (2 * GT)            // A, B = 32768
#define GEMM_SMEM (3 * GSTAGE)       // 98304

template<int MODE>
__global__ void __launch_bounds__(256, 2) gemm_f16(
    const __half* __restrict__ A, const __half* __restrict__ BT,
    const float* __restrict__ bias, float* __restrict__ C, int Nc, int K,
    __half* qf_, __half* kf_, __half* vf_)
{
    extern __shared__ char gsm[];
    const uint32_t sb = smem_u32(gsm);
    const int tid = threadIdx.x, wid = tid >> 5, lid = tid & 31;
    const int wm = wid >> 1, wn = wid & 1;
    const int m0 = blockIdx.y << 7, n0 = blockIdx.x << 7;

    const __half* pA = A  + (size_t)m0 * K;
    const __half* pB = BT + (size_t)n0 * K;

    float acc[2][8][4];
#pragma unroll
    for (int i = 0; i < 2; ++i)
#pragma unroll
        for (int j = 0; j < 8; ++j)
#pragma unroll
            for (int k = 0; k < 4; ++k) acc[i][j][k] = 0.f;

    const int nkt = K >> 6;   // BK = 64

    const int prow = tid >> 3, pc = tid & 7;
#define GPF(kt, stage) do {                                                      \
    uint32_t s0 = sb + (stage) * GSTAGE;                                         \
    _Pragma("unroll")                                                            \
    for (int hf = 0; hf < 4; ++hf) {                                             \
        int row = prow + hf * 32;                                                \
        uint32_t d = s0 + row * 128 + ((pc ^ (row & 7)) << 4);                   \
        size_t go = (size_t)row * K + (size_t)(kt) * 64 + pc * 8;                \
        CP_ASYNC16(d,      pA + go);                                             \
        CP_ASYNC16(d + GT, pB + go);                                             \
    }                                                                            \
    CP_COMMIT();                                                                 \
} while (0)

    GPF(0, 0);
    GPF(1, 1);

    uint32_t abase[2], asw[2], bbase[4], bsw[4];
    const int acb = lid >> 4;
    const int bcb = (lid >> 3) & 1;
#pragma unroll
    for (int im = 0; im < 2; ++im) {
        int ar = wm * 32 + (lid & 15) + im * 16;
        abase[im] = ar * 128;
        asw[im] = ar & 7;
    }
#pragma unroll
    for (int p = 0; p < 4; ++p) {
        int br = wn * 64 + (lid & 7) + ((lid >> 4) << 3) + p * 16;
        bbase[p] = br * 128;
        bsw[p] = br & 7;
    }

    int scur = 0;
    for (int kt = 0; kt < nkt; ++kt) {
        if (kt == nkt - 1) { CP_WAIT(0); } else { CP_WAIT(1); }
        __syncthreads();
        const uint32_t st = sb + scur * GSTAGE;

#pragma unroll
        for (int kc = 0; kc < 4; ++kc) {
            uint32_t ah[2][4];
#pragma unroll
            for (int im = 0; im < 2; ++im)
                ldsm_x4(ah[im], st + abase[im]
                                + (((uint32_t)(kc * 2 + acb) ^ asw[im]) << 4));
#pragma unroll
            for (int p = 0; p < 4; ++p) {
                uint32_t b4[4];
                ldsm_x4(b4, st + GT + bbase[p]
                            + (((uint32_t)(kc * 2 + bcb) ^ bsw[p]) << 4));
                const int nt0 = p * 2, nt1 = p * 2 + 1;
                mma_f16(acc[0][nt0], ah[0], b4[0], b4[1]);
                mma_f16(acc[1][nt0], ah[1], b4[0], b4[1]);
                mma_f16(acc[0][nt1], ah[0], b4[2], b4[3]);
                mma_f16(acc[1][nt1], ah[1], b4[2], b4[3]);
            }
        }
        if (kt + 2 < nkt) {
            int spf = scur + 2; if (spf >= 3) spf -= 3;
            GPF(kt + 2, spf);
        }
        if (++scur == 3) scur = 0;
    }
#undef GPF

    const int g = lid >> 2, q = lid & 3;
    if (MODE == 0) {
#pragma unroll
        for (int im = 0; im < 2; ++im) {
            const int row0 = m0 + wm * 32 + im * 16 + g;
#pragma unroll
            for (int nt = 0; nt < 8; ++nt) {
                const int col = n0 + wn * 64 + nt * 8 + q * 2;
                float b0 = 0.f, b1 = 0.f;
                if (bias) { b0 = bias[col]; b1 = bias[col + 1]; }
                float2 v0 = make_float2(acc[im][nt][0] + b0, acc[im][nt][1] + b1);
                float2 v1 = make_float2(acc[im][nt][2] + b0, acc[im][nt][3] + b1);
                *(float2*)(C + (size_t)row0 * Nc + col)       = v0;
                *(float2*)(C + (size_t)(row0 + 8) * Nc + col) = v1;
            }
        }
    } else {
        // fp16 qkv epilogue; q pre-scaled by 0.125*log2(e) for exp2-softmax
#pragma unroll
        for (int im = 0; im < 2; ++im) {
            const int row0 = m0 + wm * 32 + im * 16 + g;
#pragma unroll
            for (int nt = 0; nt < 8; ++nt) {
                const int col = n0 + wn * 64 + nt * 8 + q * 2;
                const int sect = col / 768, rem = col - sect * 768;
                const int h = rem >> 6, d = rem & 63;
                __half* dst;
                float sc;
                if (sect == 0)      { dst = qf_; sc = 0.18033688f; }
                else if (sect == 1) { dst = kf_; sc = 1.0f; }
                else                { dst = vf_; sc = 1.0f; }
#pragma unroll
                for (int rr = 0; rr < 2; ++rr) {
                    const int row = row0 + rr * 8;
                    uint32_t hh = pack_f16x2(acc[im][nt][rr * 2 + 0] * sc,
                                             acc[im][nt][rr * 2 + 1] * sc);
                    size_t off = ((size_t)(row >> 10) * 12 + h) * 65536
                               + (size_t)(row & 1023) * 64 + d;
                    *(uint32_t*)(dst + off) = hh;
                }
            }
        }
    }
}

// ---------------- fp16 flash attention (Bk=128; R15 form) -------------------
#define AT2     16384                // one K or V tile (128 rows x 128B fp16)
#define ASTG    (2 * AT2)            // K, V = 32768
#define ATTN_SMEM (3 * ASTG)         // 98304

__global__ void __launch_bounds__(256, 2) attn_hmma(
    const __half* __restrict__ qf_, const __half* __restrict__ kf_,
    const __half* __restrict__ vf_, __half* __restrict__ af_)
{
    extern __shared__ char sm_[];
    const uint32_t sb = smem_u32(sm_);
    const int tid = threadIdx.x, wid = tid >> 5, lid = tid & 31;
    const int g = lid >> 2, q = lid & 3;
    const int bh = blockIdx.y, qt = blockIdx.x;

    const size_t hb = (size_t)bh << 16;
    const __half* Qf = qf_ + hb + (size_t)qt * 128 * 64;
    const __half* Kf = kf_ + hb;
    const __half* Vf = vf_ + hb;

#pragma unroll
    for (int it = 0; it < 4; ++it) {
        int idx = tid + it * 256;
        int row = idx >> 3, c = idx & 7;
        uint32_t d = row * 128 + ((c ^ (row & 7)) << 4);
        *(uint4*)(sm_ + d) = *(const uint4*)(Qf + (size_t)row * 64 + c * 8);
    }
    __syncthreads();

    uint32_t qf[4][4];
    {
        const int arq = wid * 16 + (lid & 15);
        const uint32_t qbase = arq * 128;
        const uint32_t qsw = arq & 7;
        const int acb = lid >> 4;
#pragma unroll
        for (int kc = 0; kc < 4; ++kc)
            ldsm_x4(qf[kc], sb + qbase + (((uint32_t)(kc * 2 + acb) ^ qsw) << 4));
    }
    __syncthreads();

    float lrow[2] = {0.f, 0.f};
    float o[8][4];
#pragma unroll
    for (int i = 0; i < 8; ++i)
#pragma unroll
        for (int j = 0; j < 4; ++j) o[i][j] = 0.f;

    const int prow = tid >> 3, pc = tid & 7;
#define APF(kt, stage) do {                                                       \
    uint32_t s0 = sb + (stage) * ASTG;                                            \
    _Pragma("unroll")                                                             \
    for (int hf = 0; hf < 4; ++hf) {                                              \
        int row = prow + hf * 32;                                                 \
        uint32_t d = s0 + row * 128 + ((pc ^ (row & 7)) << 4);                    \
        size_t go = (size_t)((kt) * 128 + row) * 64 + pc * 8;                     \
        CP_ASYNC16(d,       Kf + go);                                             \
        CP_ASYNC16(d + AT2, Vf + go);                                             \
    }                                                                             \
    CP_COMMIT();                                                                  \
} while (0)

    APF(0, 0);
    APF(1, 1);

    uint32_t kbase[4], ksw[4], vbase[4], vsw[4];
    const int bcb = (lid >> 3) & 1;
    const int vcb = lid >> 4;
#pragma unroll
    for (int p = 0; p < 4; ++p) {
        int br = (lid & 7) + ((lid >> 4) << 3) + p * 16;
        kbase[p] = br * 128; ksw[p] = br & 7;
        int vr = (lid & 15) + p * 16;
        vbase[p] = vr * 128; vsw[p] = vr & 7;
    }

    int scur = 0;
    for (int kt = 0; kt < 8; ++kt) {
        if (kt == 7) { CP_WAIT(0); } else { CP_WAIT(1); }
        __syncthreads();
        const uint32_t st = sb + scur * ASTG;

#pragma unroll
        for (int half = 0; half < 2; ++half) {
            const uint32_t ho = half * 8192;   // 64 key-rows * 128B

            // ---- S = Q K^T (fp16), 32 MMAs ----
            float s[8][4];
#pragma unroll
            for (int i = 0; i < 8; ++i)
#pragma unroll
                for (int j = 0; j < 4; ++j) s[i][j] = 0.f;

#pragma unroll
            for (int kc = 0; kc < 4; ++kc) {
#pragma unroll
                for (int p = 0; p < 4; ++p) {
                    uint32_t kh4[4];
                    ldsm_x4(kh4, st + ho + kbase[p]
                                 + (((uint32_t)(kc * 2 + bcb) ^ ksw[p]) << 4));
                    mma_f16(s[2 * p],     qf[kc], kh4[0], kh4[1]);
                    mma_f16(s[2 * p + 1], qf[kc], kh4[2], kh4[3]);
                }
            }

            uint32_t pab[2][4];
#define PREP(t, buf) do {                                                         \
            float a0 = exp2f(s[2*(t)][0]),   a1 = exp2f(s[2*(t)][1]);             \
            float a2 = exp2f(s[2*(t)][2]),   a3 = exp2f(s[2*(t)][3]);             \
            float b0 = exp2f(s[2*(t)+1][0]), b1 = exp2f(s[2*(t)+1][1]);           \
            float b2 = exp2f(s[2*(t)+1][2]), b3 = exp2f(s[2*(t)+1][3]);           \
            lrow[0] += a0 + a1 + b0 + b1;                                         \
            lrow[1] += a2 + a3 + b2 + b3;                                         \
            pab[buf][0] = pack_f16x2(a0, a1);                                     \
            pab[buf][1] = pack_f16x2(a2, a3);                                     \
            pab[buf][2] = pack_f16x2(b0, b1);                                     \
            pab[buf][3] = pack_f16x2(b2, b3);                                     \
} while (0)

            PREP(0, 0);

            // ---- O += P V (fp16); exp(t+1) hides under MMAs ----
#pragma unroll
            for (int t = 0; t < 4; ++t) {
                const int cur = t & 1;
#pragma unroll
                for (int p = 0; p < 2; ++p) {
                    uint32_t vh4[4];
                    ldsm_x4_t(vh4, st + AT2 + ho + vbase[t]
                                   + (((uint32_t)(p * 2 + vcb) ^ vsw[t]) << 4));
                    mma_f16(o[2 * p],     pab[cur], vh4[0], vh4[1]);
                    mma_f16(o[2 * p + 1], pab[cur], vh4[2], vh4[3]);
                }
                if (t < 3) PREP(t + 1, cur ^ 1);
#pragma unroll
                for (int p = 2; p < 4; ++p) {
                    uint32_t vh4[4];
                    ldsm_x4_t(vh4, st + AT2 + ho + vbase[t]
                                   + (((uint32_t)(p * 2 + vcb) ^ vsw[t]) << 4));
                    mma_f16(o[2 * p],     pab[cur], vh4[0], vh4[1]);
                    mma_f16(o[2 * p + 1], pab[cur], vh4[2], vh4[3]);
                }
            }
#undef PREP
        }

        if (kt + 2 < 8) {
            int spf = scur + 2; if (spf >= 3) spf -= 3;
            APF(kt + 2, spf);
        }
        if (++scur == 3) scur = 0;
    }
#undef APF

    // ---- epilogue: one row-sum reduction, normalize, fp16 write ----
#pragma unroll
    for (int r = 0; r < 2; ++r) {
        lrow[r] += __shfl_xor_sync(0xffffffffu, lrow[r], 1);
        lrow[r] += __shfl_xor_sync(0xffffffffu, lrow[r], 2);
    }
    const int b = bh / NH_, h = bh - b * NH_;
    const float inv0 = 1.f / lrow[0], inv1 = 1.f / lrow[1];
    const int row0 = b * 1024 + qt * 128 + wid * 16 + g;
#pragma unroll
    for (int nt = 0; nt < 8; ++nt) {
        const int col = h * 64 + nt * 8 + q * 2;
        uint32_t hh = pack_f16x2(o[nt][0] * inv0, o[nt][1] * inv0);
        *(uint32_t*)(af_ + (size_t)row0 * DIM_ + col) = hh;
        hh = pack_f16x2(o[nt][2] * inv1, o[nt][3] * inv1);
        *(uint32_t*)(af_ + (size_t)(row0 + 8) * DIM_ + col) = hh;
    }
}

// ---------------------------------------------------------------------------
extern "C" void kernel_launch(void* const* d_in, const int* in_sizes, int n_in,
                              void* d_out, int out_size)
{
    const float* x      = (const float*)d_in[0];
    const float* w_qkv  = (const float*)d_in[1];
    const float* w_proj = (const float*)d_in[2];
    const float* b_proj = (const float*)d_in[3];
    float* out = (float*)d_out;

    __half *xf, *af, *wqT, *wpT, *qf, *kf, *vf;
    cudaGetSymbolAddress((void**)&xf, g_xf);
    cudaGetSymbolAddress((void**)&af, g_af);
    cudaGetSymbolAddress((void**)&wqT, g_wqT);
    cudaGetSymbolAddress((void**)&wpT, g_wpT);
    cudaGetSymbolAddress((void**)&qf, g_qf);
    cudaGetSymbolAddress((void**)&kf, g_kf);
    cudaGetSymbolAddress((void**)&vf, g_vf);

    cudaFuncSetAttribute((const void*)gemm_f16<1>,
        cudaFuncAttributeMaxDynamicSharedMemorySize, GEMM_SMEM);
    cudaFuncSetAttribute((const void*)gemm_f16<0>,
        cudaFuncAttributeMaxDynamicSharedMemorySize, GEMM_SMEM);
    cudaFuncSetAttribute((const void*)attn_hmma,
        cudaFuncAttributeMaxDynamicSharedMemorySize, ATTN_SMEM);

    const int M = MROWS;

    // 0) prologue v2 (fat blocks: 1536 x-convert + 576 transpose tiles)
    prologue<<<2112, 256>>>(x, w_qkv, w_proj, xf, wqT, wpT);

    // 1) QKV projection (fp16, BK=64) -> fp16 per-head q/k/v (q pre-scaled)
    gemm_f16<1><<<dim3(QKVC_ / 128, M / 128), 256, GEMM_SMEM>>>(
        xf, wqT, nullptr, nullptr, QKVC_, DIM_, qf, kf, vf);

    // 2) fp16 flash attention (Bk=128) -> fp16 proj input
    attn_hmma<<<dim3(N_ / 128, B_ * NH_), 256, ATTN_SMEM>>>(
        qf, kf, vf, af);

    // 3) output projection (fp16, BK=64) + bias -> out
    gemm_f16<0><<<dim3(DIM_ / 128, M / 128), 256, GEMM_SMEM>>>(
        af, wpT, b_proj, out, DIM_, DIM_, nullptr, nullptr, nullptr);
}